// round 13
// baseline (speedup 1.0000x reference)
#include <cuda_runtime.h>
#include <math.h>

// Problem constants
#define BB   8
#define NN   20000
#define NPAD 20480        // 160 * 128
#define QTR  (NPAD/4)
#define PP   256
#define SS   32
#define CC   256
#define NCC  18
#define BP   (BB*PP)      // 2048
#define STR0 264          // point-major gather row stride (floats)
#define OS   68           // channel-major hidden row stride (floats)

typedef unsigned long long ull;

// packed f32x2 helpers (sm_103a)
#define FMA_F32X2(a, x, w) \
    asm("fma.rn.f32x2 %0, %1, %2, %0;" : "+l"(a) : "l"(x), "l"(w))
__device__ __forceinline__ ull pack2(float v) {
    ull r; asm("mov.b64 %0, {%1, %1};" : "=l"(r) : "f"(v)); return r;
}
__device__ __forceinline__ ull packxy(float x, float y) {
    ull r; asm("mov.b64 %0, {%1, %2};" : "=l"(r) : "f"(x), "f"(y)); return r;
}
__device__ __forceinline__ float2 unpack2(ull a) {
    float2 f; asm("mov.b64 {%0, %1}, %2;" : "=f"(f.x), "=f"(f.y) : "l"(a)); return f;
}

// ---------------- scratch (__device__ globals; no allocation allowed) ---------------
// NOTE: never pass these as kernel arguments from host code (ATS hides the bug).
__device__ int   g_sel[BP*SS];
__device__ float g_nf [BP*128];
__device__ float g_lf [BP*256];
__device__ float g_ss [BB*256];
__device__ float g_ss2[BB*512];
__device__ __align__(16) float g_sx[BB*NPAD];
__device__ __align__(16) float g_sy[BB*NPAD];
__device__ __align__(16) float g_sz[BB*NPAD];
__device__ __align__(16) float g_ft[(size_t)BB*NN*CC];   // features transposed [b][n][c]
__device__ float g_e1[BB*128], g_e2[BB*256];
__device__ float g_t1[BB*512], g_t2[BB*1024];
__device__ float g_s1[BB*512], g_s2[BB*1024];

// transposed weights [K][O]; g_mw0t rows permuted: c<256 = feature c, 256..258 = xyz
__device__ __align__(16) float g_mw0t [259*128];
__device__ __align__(16) float g_mw1t [128*128];
__device__ __align__(16) float g_mw2t [128*128];
__device__ __align__(16) float g_lw0t [146*256];
__device__ __align__(16) float g_lw1t [256*256];
__device__ __align__(16) float g_lw2t [256*256];

__device__ __forceinline__ float gelu_exact(float x) {
    return 0.5f * x * (1.0f + erff(x * 0.70710678118654752f));
}
__device__ __forceinline__ float silu_f(float x) { return x / (1.0f + expf(-x)); }
__device__ __forceinline__ float relu_f(float x) { return fmaxf(x, 0.0f); }

// ---------------- kernel P: fused prep = xyz SoA + 6 weight transposes --------------
__global__ void k_prep(const float* __restrict__ xyz,
                       const float* __restrict__ mw0, const float* __restrict__ mw1,
                       const float* __restrict__ mw2, const float* __restrict__ lw0,
                       const float* __restrict__ lw1, const float* __restrict__ lw2) {
    int blk = blockIdx.x;
    int tx = threadIdx.x, ty = threadIdx.y;
    int tid = ty * 32 + tx;
    if (blk < 640) {
        int i = blk * 256 + tid;
        if (i >= BB * NPAD) return;
        int b = i / NPAD, n = i - b * NPAD;
        float x = 3e38f, y = 3e38f, z = 3e38f;
        if (n < NN) {
            const float* p = xyz + ((size_t)b * NN + n) * 3;
            x = p[0]; y = p[1]; z = p[2];
        }
        g_sx[i] = x; g_sy[i] = y; g_sz[i] = z;
        return;
    }
    int t = blk - 640;
    const float* src; float* dst; int O, K, base; bool perm = false;
    if      (t < 36)  { src = mw0; dst = g_mw0t; O = 128; K = 259; base = 0;   perm = true; }
    else if (t < 52)  { src = mw1; dst = g_mw1t; O = 128; K = 128; base = 36;  }
    else if (t < 68)  { src = mw2; dst = g_mw2t; O = 128; K = 128; base = 52;  }
    else if (t < 108) { src = lw0; dst = g_lw0t; O = 256; K = 146; base = 68;  }
    else if (t < 172) { src = lw1; dst = g_lw1t; O = 256; K = 256; base = 108; }
    else              { src = lw2; dst = g_lw2t; O = 256; K = 256; base = 172; }
    int tile = t - base;
    int ntk = (K + 31) >> 5;
    int kt = tile % ntk, ot = tile / ntk;
    __shared__ float s[32][33];
    int k0 = kt * 32, o0 = ot * 32;
    #pragma unroll
    for (int i = ty; i < 32; i += 8) {
        int o = o0 + i, k = k0 + tx;
        if (o < O && k < K) {
            int sk = perm ? (k < 256 ? k + 3 : k - 256) : k;
            s[i][tx] = src[o * K + sk];
        }
    }
    __syncthreads();
    #pragma unroll
    for (int i = ty; i < 32; i += 8) {
        int k = k0 + i, o = o0 + tx;
        if (k < K && o < O) dst[k * O + o] = s[tx][i];
    }
}

// ---------------- kernel F: feature transpose [C][N] -> [N][C] ----------------------
__global__ void k_ftrans(const float* __restrict__ feat) {
    __shared__ float t[32][33];
    int tx = threadIdx.x, ty = threadIdx.y;
    int n0 = blockIdx.x << 5, c0 = blockIdx.y << 5, b = blockIdx.z;
    const float* src = feat + ((size_t)(b * CC + c0)) * NN + n0;
    #pragma unroll
    for (int i = ty; i < 32; i += 8)
        t[i][tx] = src[(size_t)i * NN + tx];
    __syncthreads();
    float* dst = g_ft + ((size_t)b * NN + n0) * CC + c0;
    #pragma unroll
    for (int i = ty; i < 32; i += 8)
        dst[(size_t)i * CC + tx] = t[tx][i];
}

// ---------------- kernel A: in-box sampling, 4 warps/proposal quarter-scan + merge --
__global__ void __launch_bounds__(128) k_sample(const float* __restrict__ xyz,
                         const float* __restrict__ bsize,
                         const int*   __restrict__ inds) {
    __shared__ int buf[4][SS];
    __shared__ int cnt[4];
    int tid = threadIdx.x;
    int lane = tid & 31, w = tid >> 5;
    int q = blockIdx.x;
    int b = q >> 8;
    int n0 = inds[q];
    const float* cp = xyz + ((size_t)b * NN + n0) * 3;
    float cx = cp[0], cy = cp[1], cz = cp[2];
    float hx = bsize[q*3+0]*0.5f, hy = bsize[q*3+1]*0.5f, hz = bsize[q*3+2]*0.5f;
    const float4* X = (const float4*)(g_sx + b * NPAD);
    const float4* Y = (const float4*)(g_sy + b * NPAD);
    const float4* Z = (const float4*)(g_sz + b * NPAD);

    int vbase = w * (QTR/4);
    unsigned below = (1u << lane) - 1u;
    int found = 0;
    float4 xs = X[vbase + lane], ys = Y[vbase + lane], zs = Z[vbase + lane];
    const int ITERS = QTR / 128;                   // 40
    for (int it = 0; it < ITERS; it++) {
        float4 nx, ny, nz;
        if (it + 1 < ITERS) {
            int v = vbase + (it + 1) * 32 + lane;
            nx = X[v]; ny = Y[v]; nz = Z[v];
        }
        bool i0 = (fabsf(xs.x-cx)<=hx) && (fabsf(ys.x-cy)<=hy) && (fabsf(zs.x-cz)<=hz);
        bool i1 = (fabsf(xs.y-cx)<=hx) && (fabsf(ys.y-cy)<=hy) && (fabsf(zs.y-cz)<=hz);
        bool i2 = (fabsf(xs.z-cx)<=hx) && (fabsf(ys.z-cy)<=hy) && (fabsf(zs.z-cz)<=hz);
        bool i3 = (fabsf(xs.w-cx)<=hx) && (fabsf(ys.w-cy)<=hy) && (fabsf(zs.w-cz)<=hz);
        unsigned m0 = __ballot_sync(0xffffffffu, i0);
        unsigned m1 = __ballot_sync(0xffffffffu, i1);
        unsigned m2 = __ballot_sync(0xffffffffu, i2);
        unsigned m3 = __ballot_sync(0xffffffffu, i3);
        if (m0 | m1 | m2 | m3) {
            int pre = found
                    + __popc(m0 & below) + __popc(m1 & below)
                    + __popc(m2 & below) + __popc(m3 & below);
            int np = w * QTR + it * 128 + 4 * lane;
            unsigned b0 = (m0 >> lane) & 1u, b1 = (m1 >> lane) & 1u, b2 = (m2 >> lane) & 1u;
            if (i0 && pre < SS)                    buf[w][pre] = np;
            int r1 = pre + (int)b0;
            if (i1 && r1 < SS)                     buf[w][r1] = np + 1;
            int r2 = r1 + (int)b1;
            if (i2 && r2 < SS)                     buf[w][r2] = np + 2;
            int r3 = r2 + (int)b2;
            if (i3 && r3 < SS)                     buf[w][r3] = np + 3;
        }
        found += __popc(m0) + __popc(m1) + __popc(m2) + __popc(m3);
        if (found >= SS) break;
        xs = nx; ys = ny; zs = nz;
    }
    if (lane == 0) cnt[w] = found;
    __syncthreads();

    if (tid < 32) {
        int c0 = cnt[0], c1 = cnt[1], c2 = cnt[2], c3 = cnt[3];
        int s0 = c0 < SS ? c0 : SS;
        int s1 = c1 < SS ? c1 : SS;
        int s2 = c2 < SS ? c2 : SS;
        int total = c0 + c1 + c2 + c3;
        int eff = total < SS ? total : SS;
        int sel = 0;
        if (eff > 0) {
            int j = tid % eff;
            if (j < s0) sel = buf[0][j];
            else { j -= s0;
                if (j < s1) sel = buf[1][j];
                else { j -= s1;
                    if (j < s2) sel = buf[2][j];
                    else sel = buf[3][j - s2];
                }
            }
        }
        g_sel[q*SS + tid] = sel;
    }
}

// ---------------- time-MLP chain -----------------------------------------------------
__global__ void k_emb(const float* __restrict__ ts) {
    int b = blockIdx.x, tid = threadIdx.x;
    float t = ts[b];
    if (tid < 64) {
        float f = expf(tid * (-9.210340371976184f/63.0f));
        float e = t * f;
        g_e1[b*128 + tid] = sinf(e); g_e1[b*128 + 64 + tid] = cosf(e);
    }
    {
        float f = expf(tid * (-9.210340371976184f/127.0f));
        float e = t * f;
        g_e2[b*256 + tid] = sinf(e); g_e2[b*256 + 128 + tid] = cosf(e);
    }
}

__global__ void k_tstage(const float* __restrict__ WA, const float* __restrict__ bA,
                         const float* __restrict__ WB, const float* __restrict__ bB,
                         int RA, int stage) {
    extern __shared__ float dsm[];
    int blk = blockIdx.x;
    int nA = RA >> 5;
    bool isA = blk < nA;
    const float *W = isA ? WA : WB;
    const float *bias = isA ? bA : bB;
    int row0 = (isA ? blk : blk - nA) << 5;
    const float* gin; float* gout; int K, R; int act;
    if (stage == 0) {
        act = 0;
        if (isA) { gin = g_e1; gout = g_t1; K = 128;  R = 512;  }
        else     { gin = g_e2; gout = g_t2; K = 256;  R = 1024; }
    } else if (stage == 1) {
        act = 1;
        if (isA) { gin = g_t1; gout = g_s1; K = 512;  R = 512;  }
        else     { gin = g_t2; gout = g_s2; K = 1024; R = 1024; }
    } else {
        act = 2;
        if (isA) { gin = g_s1; gout = g_ss;  K = 512;  R = 256; }
        else     { gin = g_s2; gout = g_ss2; K = 1024; R = 512; }
    }
    float* in_s = dsm;
    float* w_s  = dsm + 8 * (K + 4);
    int tid = threadIdx.x;
    int rl = tid >> 3, bb = tid & 7;
    int stride = K + 4;
    int ksh = __ffs(K) - 1;
    for (int i = tid; i < (K << 3); i += 256) {
        int b2 = i >> ksh, c = i & (K - 1);
        in_s[b2 * stride + c] = gin[i];
    }
    float acc = 0.0f;
    for (int ko = 0; ko < K; ko += 128) {
        __syncthreads();
        #pragma unroll
        for (int i = tid; i < 1024; i += 256) {
            int r = i >> 5, c4 = i & 31;
            float4 v = *(const float4*)(W + (size_t)(row0 + r) * K + ko + c4 * 4);
            *(float4*)&w_s[r * 132 + c4 * 4] = v;
        }
        __syncthreads();
        const float* wr = w_s + rl * 132;
        const float* ir = in_s + bb * stride + ko;
        #pragma unroll 8
        for (int c = 0; c < 128; c++) acc += wr[c] * ir[c];
    }
    acc += bias[row0 + rl];
    if (act == 0) acc = gelu_exact(acc);
    else if (act == 1) acc = silu_f(acc);
    gout[bb * R + row0 + rl] = acc;
}

// ---------------- kernel B: gather + f32x2 point MLP + maxpool + label MLP ----------
// Block = 2 proposals (64 pts) x 128 outs; 128 threads; thread = 8 pts x 8 outs.
// acc = 32 x b64 (f32x2 over point pairs). Layer0 input point-major, swizzled by
// chunk ^ (s>>3) (3-bit key, chunk high bits preserved); layers 1-2 channel-major.

// layers 1/2: channel-major input
__device__ __forceinline__ void layerF2(const float* __restrict__ in,   // [128][OS]
                                        const float* __restrict__ wt,   // [128][128]
                                        const float* __restrict__ bias,
                                        float* __restrict__ out,        // [128][OS]
                                        int pg, int oh) {
    ull acc[32];
    {
        float4 b0 = *(const float4*)(bias + 8*oh);
        float4 b1 = *(const float4*)(bias + 8*oh + 4);
        ull p;
        p = pack2(b0.x); acc[0]=p;  acc[1]=p;  acc[2]=p;  acc[3]=p;
        p = pack2(b0.y); acc[4]=p;  acc[5]=p;  acc[6]=p;  acc[7]=p;
        p = pack2(b0.z); acc[8]=p;  acc[9]=p;  acc[10]=p; acc[11]=p;
        p = pack2(b0.w); acc[12]=p; acc[13]=p; acc[14]=p; acc[15]=p;
        p = pack2(b1.x); acc[16]=p; acc[17]=p; acc[18]=p; acc[19]=p;
        p = pack2(b1.y); acc[20]=p; acc[21]=p; acc[22]=p; acc[23]=p;
        p = pack2(b1.z); acc[24]=p; acc[25]=p; acc[26]=p; acc[27]=p;
        p = pack2(b1.w); acc[28]=p; acc[29]=p; acc[30]=p; acc[31]=p;
    }
    const float* ip = in + 8*pg;
    const float* wp = wt + 8*oh;
    #pragma unroll 2
    for (int c = 0; c < 128; c++) {
        ulonglong2 xa = *(const ulonglong2*)(ip + c*OS);
        ulonglong2 xb = *(const ulonglong2*)(ip + c*OS + 4);
        ull x0 = xa.x, x1 = xa.y, x2 = xb.x, x3 = xb.y;
        float4 w0 = *(const float4*)(wp + c*128);
        float4 w1 = *(const float4*)(wp + c*128 + 4);
        ull wq;
        wq = pack2(w0.x);
        FMA_F32X2(acc[0],  x0, wq); FMA_F32X2(acc[1],  x1, wq);
        FMA_F32X2(acc[2],  x2, wq); FMA_F32X2(acc[3],  x3, wq);
        wq = pack2(w0.y);
        FMA_F32X2(acc[4],  x0, wq); FMA_F32X2(acc[5],  x1, wq);
        FMA_F32X2(acc[6],  x2, wq); FMA_F32X2(acc[7],  x3, wq);
        wq = pack2(w0.z);
        FMA_F32X2(acc[8],  x0, wq); FMA_F32X2(acc[9],  x1, wq);
        FMA_F32X2(acc[10], x2, wq); FMA_F32X2(acc[11], x3, wq);
        wq = pack2(w0.w);
        FMA_F32X2(acc[12], x0, wq); FMA_F32X2(acc[13], x1, wq);
        FMA_F32X2(acc[14], x2, wq); FMA_F32X2(acc[15], x3, wq);
        wq = pack2(w1.x);
        FMA_F32X2(acc[16], x0, wq); FMA_F32X2(acc[17], x1, wq);
        FMA_F32X2(acc[18], x2, wq); FMA_F32X2(acc[19], x3, wq);
        wq = pack2(w1.y);
        FMA_F32X2(acc[20], x0, wq); FMA_F32X2(acc[21], x1, wq);
        FMA_F32X2(acc[22], x2, wq); FMA_F32X2(acc[23], x3, wq);
        wq = pack2(w1.z);
        FMA_F32X2(acc[24], x0, wq); FMA_F32X2(acc[25], x1, wq);
        FMA_F32X2(acc[26], x2, wq); FMA_F32X2(acc[27], x3, wq);
        wq = pack2(w1.w);
        FMA_F32X2(acc[28], x0, wq); FMA_F32X2(acc[29], x1, wq);
        FMA_F32X2(acc[30], x2, wq); FMA_F32X2(acc[31], x3, wq);
    }
    float* o = out + 8*pg;
    #pragma unroll
    for (int j = 0; j < 8; j++) {
        float2 f0 = unpack2(acc[j*4+0]);
        float2 f1 = unpack2(acc[j*4+1]);
        float2 f2 = unpack2(acc[j*4+2]);
        float2 f3 = unpack2(acc[j*4+3]);
        *(float4*)(o + (8*oh+j)*OS)     =
            make_float4(relu_f(f0.x), relu_f(f0.y), relu_f(f1.x), relu_f(f1.y));
        *(float4*)(o + (8*oh+j)*OS + 4) =
            make_float4(relu_f(f2.x), relu_f(f2.y), relu_f(f3.x), relu_f(f3.y));
    }
}

// layer 0: point-major swizzled input (256 feature channels + 3 xyz)
__device__ __forceinline__ void layer0F2(const float* __restrict__ in,   // gpm
                                         const float* __restrict__ wt,   // g_mw0t
                                         const float* __restrict__ bias,
                                         float* __restrict__ out,
                                         int pg, int oh) {
    ull acc[32];
    {
        float4 b0 = *(const float4*)(bias + 8*oh);
        float4 b1 = *(const float4*)(bias + 8*oh + 4);
        ull p;
        p = pack2(b0.x); acc[0]=p;  acc[1]=p;  acc[2]=p;  acc[3]=p;
        p = pack2(b0.y); acc[4]=p;  acc[5]=p;  acc[6]=p;  acc[7]=p;
        p = pack2(b0.z); acc[8]=p;  acc[9]=p;  acc[10]=p; acc[11]=p;
        p = pack2(b0.w); acc[12]=p; acc[13]=p; acc[14]=p; acc[15]=p;
        p = pack2(b1.x); acc[16]=p; acc[17]=p; acc[18]=p; acc[19]=p;
        p = pack2(b1.y); acc[20]=p; acc[21]=p; acc[22]=p; acc[23]=p;
        p = pack2(b1.z); acc[24]=p; acc[25]=p; acc[26]=p; acc[27]=p;
        p = pack2(b1.w); acc[28]=p; acc[29]=p; acc[30]=p; acc[31]=p;
    }
    const float* ip = in + 8*pg*STR0;
    const float* wp = wt + 8*oh;
    #pragma unroll 2
    for (int c = 0; c < 259; c++) {
        // 3-bit XOR key on the 16B-chunk index; chunk high bits PRESERVED
        int t = (c < 256) ? ((((c >> 2) ^ pg) << 2) | (c & 3)) : c;
        float xa = ip[0*STR0 + t], xb = ip[1*STR0 + t];
        float xc = ip[2*STR0 + t], xd = ip[3*STR0 + t];
        float xe = ip[4*STR0 + t], xf = ip[5*STR0 + t];
        float xg = ip[6*STR0 + t], xh = ip[7*STR0 + t];
        ull x0 = packxy(xa, xb), x1 = packxy(xc, xd);
        ull x2 = packxy(xe, xf), x3 = packxy(xg, xh);
        float4 w0 = *(const float4*)(wp + c*128);
        float4 w1 = *(const float4*)(wp + c*128 + 4);
        ull wq;
        wq = pack2(w0.x);
        FMA_F32X2(acc[0],  x0, wq); FMA_F32X2(acc[1],  x1, wq);
        FMA_F32X2(acc[2],  x2, wq); FMA_F32X2(acc[3],  x3, wq);
        wq = pack2(w0.y);
        FMA_F32X2(acc[4],  x0, wq); FMA_F32X2(acc[5],  x1, wq);
        FMA_F32X2(acc[6],  x2, wq); FMA_F32X2(acc[7],  x3, wq);
        wq = pack2(w0.z);
        FMA_F32X2(acc[8],  x0, wq); FMA_F32X2(acc[9],  x1, wq);
        FMA_F32X2(acc[10], x2, wq); FMA_F32X2(acc[11], x3, wq);
        wq = pack2(w0.w);
        FMA_F32X2(acc[12], x0, wq); FMA_F32X2(acc[13], x1, wq);
        FMA_F32X2(acc[14], x2, wq); FMA_F32X2(acc[15], x3, wq);
        wq = pack2(w1.x);
        FMA_F32X2(acc[16], x0, wq); FMA_F32X2(acc[17], x1, wq);
        FMA_F32X2(acc[18], x2, wq); FMA_F32X2(acc[19], x3, wq);
        wq = pack2(w1.y);
        FMA_F32X2(acc[20], x0, wq); FMA_F32X2(acc[21], x1, wq);
        FMA_F32X2(acc[22], x2, wq); FMA_F32X2(acc[23], x3, wq);
        wq = pack2(w1.z);
        FMA_F32X2(acc[24], x0, wq); FMA_F32X2(acc[25], x1, wq);
        FMA_F32X2(acc[26], x2, wq); FMA_F32X2(acc[27], x3, wq);
        wq = pack2(w1.w);
        FMA_F32X2(acc[28], x0, wq); FMA_F32X2(acc[29], x1, wq);
        FMA_F32X2(acc[30], x2, wq); FMA_F32X2(acc[31], x3, wq);
    }
    float* o = out + 8*pg;
    #pragma unroll
    for (int j = 0; j < 8; j++) {
        float2 f0 = unpack2(acc[j*4+0]);
        float2 f1 = unpack2(acc[j*4+1]);
        float2 f2 = unpack2(acc[j*4+2]);
        float2 f3 = unpack2(acc[j*4+3]);
        *(float4*)(o + (8*oh+j)*OS)     =
            make_float4(relu_f(f0.x), relu_f(f0.y), relu_f(f1.x), relu_f(f1.y));
        *(float4*)(o + (8*oh+j)*OS + 4) =
            make_float4(relu_f(f2.x), relu_f(f2.y), relu_f(f3.x), relu_f(f3.y));
    }
}

__global__ void __launch_bounds__(128, 2) k_mlp(
                      const float* __restrict__ xyz,
                      const int* __restrict__ inds,
                      const float* __restrict__ mb0, const float* __restrict__ mb1,
                      const float* __restrict__ mb2,
                      const float* __restrict__ blabel,
                      const float* __restrict__ lb0, const float* __restrict__ lb1,
                      const float* __restrict__ lb2) {
    extern __shared__ float sm[];
    float* gpm = sm;                    // [64][STR0] gather; reused as hB [128][OS]
    float* hA  = sm + 64*STR0;          // [128][OS]
    __shared__ int   sidx[64];
    __shared__ float ctr[2][3];
    __shared__ float in0[2][152];
    __shared__ float hL1[2][256], hL2[2][256];

    int q0 = blockIdx.x * 2, b = q0 >> 8;
    int tid = threadIdx.x;              // 128 threads
    if (tid < 64) sidx[tid] = g_sel[(q0 + (tid >> 5))*SS + (tid & 31)];
    if (tid < 6) {
        int pr = tid / 3, d = tid - pr*3;
        int n0 = inds[q0 + pr];
        ctr[pr][d] = xyz[((size_t)b*NN + n0)*3 + d];
    }
    if (tid < 2*NCC) {
        int pr = tid / NCC, c = tid - pr*NCC;
        in0[pr][c] = blabel[(q0 + pr)*NCC + c];
    }
    __syncthreads();

    // gather: 64 points x 64 float4 chunks, coalesced rows, swizzle chunk ^ (s>>3)
    const float* ftb = g_ft + (size_t)b * NN * CC;
    #pragma unroll 4
    for (int i = tid; i < 64*64; i += 128) {
        int s = i >> 6, c4 = i & 63;
        float4 v = *(const float4*)(ftb + (size_t)sidx[s]*CC + (c4 << 2));
        int cc = c4 ^ (s >> 3);          // key < 8 -> affects only low 3 bits
        *(float4*)(gpm + s*STR0 + (cc << 2)) = v;
    }
    if (tid < 64) {                      // each thread fills all 3 xyz dims
        int s = tid, pr = s >> 5;
        const float* p = xyz + ((size_t)b*NN + sidx[s])*3;
        #pragma unroll
        for (int d = 0; d < 3; d++)
            gpm[s*STR0 + 256 + d] = p[d] - ctr[pr][d];
    }
    __syncthreads();

    int pg = tid & 7, oh = tid >> 3;    // pg in [0,8), oh in [0,16)
    layer0F2(gpm, g_mw0t, mb0, hA, pg, oh);      __syncthreads();
    layerF2(hA, g_mw1t, mb1, gpm, pg, oh);       __syncthreads();
    layerF2(gpm, g_mw2t, mb2, hA, pg, oh);       __syncthreads();

    // maxpool over 32 samples per proposal (relu outputs >= 0); 128 threads = 128 ch
    {
        int o = tid;
        #pragma unroll
        for (int pr = 0; pr < 2; pr++) {
            const float* r = hA + o*OS + pr*32;
            float m = 0.0f;
            #pragma unroll
            for (int j = 0; j < 32; j += 4) {
                float4 v = *(const float4*)(r + j);
                m = fmaxf(m, fmaxf(fmaxf(v.x, v.y), fmaxf(v.z, v.w)));
            }
            g_nf[(q0 + pr)*128 + o] = m;
            in0[pr][NCC + o] = m;
        }
    }
    __syncthreads();

    // fused label MLP: 146 -> 256 -> 256 -> 256; 128 threads, 2 outs x 2 proposals
    {
        int o = tid;                         // outputs o and o+128
        float a00 = lb0[o], a01 = lb0[o+128], a10 = a00, a11 = a01;
        #pragma unroll 2
        for (int c = 0; c < 146; c++) {
            float w0 = g_lw0t[c*256 + o], w1 = g_lw0t[c*256 + o + 128];
            float i0v = in0[0][c], i1v = in0[1][c];
            a00 += i0v * w0; a01 += i0v * w1;
            a10 += i1v * w0; a11 += i1v * w1;
        }
        hL1[0][o] = relu_f(a00); hL1[0][o+128] = relu_f(a01);
        hL1[1][o] = relu_f(a10); hL1[1][o+128] = relu_f(a11);
        __syncthreads();
        a00 = lb1[o]; a01 = lb1[o+128]; a10 = a00; a11 = a01;
        #pragma unroll 4
        for (int c = 0; c < 256; c++) {
            float w0 = g_lw1t[c*256 + o], w1 = g_lw1t[c*256 + o + 128];
            float i0v = hL1[0][c], i1v = hL1[1][c];
            a00 += i0v * w0; a01 += i0v * w1;
            a10 += i1v * w0; a11 += i1v * w1;
        }
        hL2[0][o] = relu_f(a00); hL2[0][o+128] = relu_f(a01);
        hL2[1][o] = relu_f(a10); hL2[1][o+128] = relu_f(a11);
        __syncthreads();
        a00 = lb2[o]; a01 = lb2[o+128]; a10 = a00; a11 = a01;
        #pragma unroll 4
        for (int c = 0; c < 256; c++) {
            float w0 = g_lw2t[c*256 + o], w1 = g_lw2t[c*256 + o + 128];
            float i0v = hL2[0][c], i1v = hL2[1][c];
            a00 += i0v * w0; a01 += i0v * w1;
            a10 += i1v * w0; a11 += i1v * w1;
        }
        g_lf[q0*256 + o]           = relu_f(a00);
        g_lf[q0*256 + o + 128]     = relu_f(a01);
        g_lf[(q0+1)*256 + o]       = relu_f(a10);
        g_lf[(q0+1)*256 + o + 128] = relu_f(a11);
    }
}

// ---------------- kernel D: FiLM + all outputs ---------------------------------------
__global__ void k_out(float* __restrict__ out, const float* __restrict__ xyz,
                      const int* __restrict__ inds) {
    const int O0 = BB*PP*3;
    const int O1 = O0 + BB*128*PP;
    const int O2 = O1 + BB*256*PP;
    const int O3 = O2 + BB*PP;
    int i = blockIdx.x * blockDim.x + threadIdx.x;
    if (i < O0) {
        int b = i / (PP*3); int r = i - b*(PP*3); int p = r/3, d = r - p*3;
        out[i] = xyz[((size_t)b*NN + inds[b*PP + p])*3 + d];
    } else if (i < O1) {
        int j = i - O0;
        int b = j >> 15;
        int r = j & 32767;
        int d = r >> 8, p = r & 255;
        int m = p & 127;
        out[i] = g_nf[((b<<8) + p)*128 + d] * (g_ss[b*256 + m] + 1.0f)
               + g_ss[b*256 + 128 + m];
    } else if (i < O2) {
        int j = i - O1;
        int b = j >> 16;
        int r = j & 65535;
        int d = r >> 8, p = r & 255;
        out[i] = g_lf[((b<<8) + p)*256 + d] * (g_ss2[b*512 + p] + 1.0f)
               + g_ss2[b*512 + 256 + p];
    } else if (i < O3) {
        out[i] = (float)inds[i - O2];
    }
}

// ---------------- launcher -----------------------------------------------------------
extern "C" void kernel_launch(void* const* d_in, const int* in_sizes, int n_in,
                              void* d_out, int out_size) {
    const float* xyz    = (const float*)d_in[0];
    const float* feat   = (const float*)d_in[1];
    const float* bsize  = (const float*)d_in[2];
    const float* blabel = (const float*)d_in[3];
    const float* ts     = (const float*)d_in[4];
    const int*   inds   = (const int*)  d_in[5];
    const float* mw0 = (const float*)d_in[6],  *mb0 = (const float*)d_in[7];
    const float* mw1 = (const float*)d_in[8],  *mb1 = (const float*)d_in[9];
    const float* mw2 = (const float*)d_in[10], *mb2 = (const float*)d_in[11];
    const float* lw0 = (const float*)d_in[12], *lb0 = (const float*)d_in[13];
    const float* lw1 = (const float*)d_in[14], *lb1 = (const float*)d_in[15];
    const float* lw2 = (const float*)d_in[16], *lb2 = (const float*)d_in[17];
    const float* tw0 = (const float*)d_in[18], *tb0 = (const float*)d_in[19];
    const float* tw1 = (const float*)d_in[20], *tb1 = (const float*)d_in[21];
    const float* bw  = (const float*)d_in[22], *bbv = (const float*)d_in[23];
    const float* tlw0= (const float*)d_in[24], *tlb0= (const float*)d_in[25];
    const float* tlw1= (const float*)d_in[26], *tlb1= (const float*)d_in[27];
    const float* blw = (const float*)d_in[28], *blb = (const float*)d_in[29];
    float* out = (float*)d_out;

    dim3 tb(32, 8);
    k_prep<<<876, tb>>>(xyz, mw0, mw1, mw2, lw0, lw1, lw2);          // 0
    k_sample<<<BP, 128>>>(xyz, bsize, inds);                         // 1
    k_ftrans<<<dim3(625, 8, 8), tb>>>(feat);                         // 2

    int smem_b = (64*STR0 + 128*OS) * (int)sizeof(float);            // 102400 B
    cudaFuncSetAttribute(k_mlp, cudaFuncAttributeMaxDynamicSharedMemorySize, smem_b);
    k_mlp<<<BP/2, 128, smem_b>>>(xyz, inds, mb0, mb1, mb2,
                                 blabel, lb0, lb1, lb2);             // 3 <- profiled

    k_emb<<<BB, 128>>>(ts);                                          // 4
    int smem_t = (8*(1024+4) + 32*132) * (int)sizeof(float);         // 49792 B
    cudaFuncSetAttribute(k_tstage, cudaFuncAttributeMaxDynamicSharedMemorySize, smem_t);
    k_tstage<<<48, 256, smem_t>>>(tw0, tb0, tlw0, tlb0, 512, 0);     // 5
    k_tstage<<<48, 256, smem_t>>>(tw1, tb1, tlw1, tlb1, 512, 1);     // 6
    k_tstage<<<24, 256, smem_t>>>(bw,  bbv, blw,  blb,  256, 2);     // 7

    const int total = BB*PP*3 + BB*128*PP + BB*256*PP + BB*PP;       // 794624
    k_out<<<(total + 255)/256, 256>>>(out, xyz, inds);               // 8
}

// round 15
// speedup vs baseline: 1.2104x; 1.2104x over previous
#include <cuda_runtime.h>
#include <math.h>

// Problem constants
#define BB   8
#define NN   20000
#define NPAD 20480        // 160 * 128
#define QTR  (NPAD/4)
#define PP   256
#define SS   32
#define CC   256
#define NCC  18
#define BP   (BB*PP)      // 2048
#define STR0 264          // point-major gather row stride (floats)
#define HST2 36           // channel-major hidden row stride (32 pts + 4 pad)

typedef unsigned long long ull;

// packed f32x2 helpers (sm_103a)
#define FMA_F32X2(a, x, w) \
    asm("fma.rn.f32x2 %0, %1, %2, %0;" : "+l"(a) : "l"(x), "l"(w))
__device__ __forceinline__ ull pack2(float v) {
    ull r; asm("mov.b64 %0, {%1, %1};" : "=l"(r) : "f"(v)); return r;
}
__device__ __forceinline__ float2 unpack2(ull a) {
    float2 f; asm("mov.b64 {%0, %1}, %2;" : "=f"(f.x), "=f"(f.y) : "l"(a)); return f;
}

// ---------------- scratch (__device__ globals; no allocation allowed) ---------------
// NOTE: never pass these as kernel arguments from host code (ATS hides the bug).
__device__ int   g_sel[BP*SS];
__device__ float g_nf [BP*128];
__device__ float g_lf [BP*256];
__device__ float g_ss [BB*256];
__device__ float g_ss2[BB*512];
__device__ __align__(16) float g_sx[BB*NPAD];
__device__ __align__(16) float g_sy[BB*NPAD];
__device__ __align__(16) float g_sz[BB*NPAD];
__device__ __align__(16) float g_ft[(size_t)BB*NN*CC];   // features transposed [b][n][c]
__device__ float g_e1[BB*128], g_e2[BB*256];
__device__ float g_t1[BB*512], g_t2[BB*1024];
__device__ float g_s1[BB*512], g_s2[BB*1024];

// transposed weights [K][O]; g_mw0t rows permuted: c<256 = feature c, 256..258 = xyz
__device__ __align__(16) float g_mw0t [259*128];
__device__ __align__(16) float g_mw1t [128*128];
__device__ __align__(16) float g_mw2t [128*128];
__device__ __align__(16) float g_lw0t [146*256];
__device__ __align__(16) float g_lw1t [256*256];
__device__ __align__(16) float g_lw2t [256*256];

__device__ __forceinline__ float gelu_exact(float x) {
    return 0.5f * x * (1.0f + erff(x * 0.70710678118654752f));
}
__device__ __forceinline__ float silu_f(float x) { return x / (1.0f + expf(-x)); }
__device__ __forceinline__ float relu_f(float x) { return fmaxf(x, 0.0f); }

// ---------------- kernel P: fused prep = xyz SoA + 6 weight transposes --------------
__global__ void k_prep(const float* __restrict__ xyz,
                       const float* __restrict__ mw0, const float* __restrict__ mw1,
                       const float* __restrict__ mw2, const float* __restrict__ lw0,
                       const float* __restrict__ lw1, const float* __restrict__ lw2) {
    int blk = blockIdx.x;
    int tx = threadIdx.x, ty = threadIdx.y;
    int tid = ty * 32 + tx;
    if (blk < 640) {
        int i = blk * 256 + tid;
        if (i >= BB * NPAD) return;
        int b = i / NPAD, n = i - b * NPAD;
        float x = 3e38f, y = 3e38f, z = 3e38f;
        if (n < NN) {
            const float* p = xyz + ((size_t)b * NN + n) * 3;
            x = p[0]; y = p[1]; z = p[2];
        }
        g_sx[i] = x; g_sy[i] = y; g_sz[i] = z;
        return;
    }
    int t = blk - 640;
    const float* src; float* dst; int O, K, base; bool perm = false;
    if      (t < 36)  { src = mw0; dst = g_mw0t; O = 128; K = 259; base = 0;   perm = true; }
    else if (t < 52)  { src = mw1; dst = g_mw1t; O = 128; K = 128; base = 36;  }
    else if (t < 68)  { src = mw2; dst = g_mw2t; O = 128; K = 128; base = 52;  }
    else if (t < 108) { src = lw0; dst = g_lw0t; O = 256; K = 146; base = 68;  }
    else if (t < 172) { src = lw1; dst = g_lw1t; O = 256; K = 256; base = 108; }
    else              { src = lw2; dst = g_lw2t; O = 256; K = 256; base = 172; }
    int tile = t - base;
    int ntk = (K + 31) >> 5;
    int kt = tile % ntk, ot = tile / ntk;
    __shared__ float s[32][33];
    int k0 = kt * 32, o0 = ot * 32;
    #pragma unroll
    for (int i = ty; i < 32; i += 8) {
        int o = o0 + i, k = k0 + tx;
        if (o < O && k < K) {
            int sk = perm ? (k < 256 ? k + 3 : k - 256) : k;
            s[i][tx] = src[o * K + sk];
        }
    }
    __syncthreads();
    #pragma unroll
    for (int i = ty; i < 32; i += 8) {
        int k = k0 + i, o = o0 + tx;
        if (k < K && o < O) dst[k * O + o] = s[tx][i];
    }
}

// ---------------- kernel F: feature transpose [C][N] -> [N][C] ----------------------
__global__ void k_ftrans(const float* __restrict__ feat) {
    __shared__ float t[32][33];
    int tx = threadIdx.x, ty = threadIdx.y;
    int n0 = blockIdx.x << 5, c0 = blockIdx.y << 5, b = blockIdx.z;
    const float* src = feat + ((size_t)(b * CC + c0)) * NN + n0;
    #pragma unroll
    for (int i = ty; i < 32; i += 8)
        t[i][tx] = src[(size_t)i * NN + tx];
    __syncthreads();
    float* dst = g_ft + ((size_t)b * NN + n0) * CC + c0;
    #pragma unroll
    for (int i = ty; i < 32; i += 8)
        dst[(size_t)i * CC + tx] = t[tx][i];
}

// ---------------- kernel A: in-box sampling, 4 warps/proposal quarter-scan + merge --
__global__ void __launch_bounds__(128) k_sample(const float* __restrict__ xyz,
                         const float* __restrict__ bsize,
                         const int*   __restrict__ inds) {
    __shared__ int buf[4][SS];
    __shared__ int cnt[4];
    int tid = threadIdx.x;
    int lane = tid & 31, w = tid >> 5;
    int q = blockIdx.x;
    int b = q >> 8;
    int n0 = inds[q];
    const float* cp = xyz + ((size_t)b * NN + n0) * 3;
    float cx = cp[0], cy = cp[1], cz = cp[2];
    float hx = bsize[q*3+0]*0.5f, hy = bsize[q*3+1]*0.5f, hz = bsize[q*3+2]*0.5f;
    const float4* X = (const float4*)(g_sx + b * NPAD);
    const float4* Y = (const float4*)(g_sy + b * NPAD);
    const float4* Z = (const float4*)(g_sz + b * NPAD);

    int vbase = w * (QTR/4);
    unsigned below = (1u << lane) - 1u;
    int found = 0;
    float4 xs = X[vbase + lane], ys = Y[vbase + lane], zs = Z[vbase + lane];
    const int ITERS = QTR / 128;                   // 40
    for (int it = 0; it < ITERS; it++) {
        float4 nx, ny, nz;
        if (it + 1 < ITERS) {
            int v = vbase + (it + 1) * 32 + lane;
            nx = X[v]; ny = Y[v]; nz = Z[v];
        }
        bool i0 = (fabsf(xs.x-cx)<=hx) && (fabsf(ys.x-cy)<=hy) && (fabsf(zs.x-cz)<=hz);
        bool i1 = (fabsf(xs.y-cx)<=hx) && (fabsf(ys.y-cy)<=hy) && (fabsf(zs.y-cz)<=hz);
        bool i2 = (fabsf(xs.z-cx)<=hx) && (fabsf(ys.z-cy)<=hy) && (fabsf(zs.z-cz)<=hz);
        bool i3 = (fabsf(xs.w-cx)<=hx) && (fabsf(ys.w-cy)<=hy) && (fabsf(zs.w-cz)<=hz);
        unsigned m0 = __ballot_sync(0xffffffffu, i0);
        unsigned m1 = __ballot_sync(0xffffffffu, i1);
        unsigned m2 = __ballot_sync(0xffffffffu, i2);
        unsigned m3 = __ballot_sync(0xffffffffu, i3);
        if (m0 | m1 | m2 | m3) {
            int pre = found
                    + __popc(m0 & below) + __popc(m1 & below)
                    + __popc(m2 & below) + __popc(m3 & below);
            int np = w * QTR + it * 128 + 4 * lane;
            unsigned b0 = (m0 >> lane) & 1u, b1 = (m1 >> lane) & 1u, b2 = (m2 >> lane) & 1u;
            if (i0 && pre < SS)                    buf[w][pre] = np;
            int r1 = pre + (int)b0;
            if (i1 && r1 < SS)                     buf[w][r1] = np + 1;
            int r2 = r1 + (int)b1;
            if (i2 && r2 < SS)                     buf[w][r2] = np + 2;
            int r3 = r2 + (int)b2;
            if (i3 && r3 < SS)                     buf[w][r3] = np + 3;
        }
        found += __popc(m0) + __popc(m1) + __popc(m2) + __popc(m3);
        if (found >= SS) break;
        xs = nx; ys = ny; zs = nz;
    }
    if (lane == 0) cnt[w] = found;
    __syncthreads();

    if (tid < 32) {
        int c0 = cnt[0], c1 = cnt[1], c2 = cnt[2], c3 = cnt[3];
        int s0 = c0 < SS ? c0 : SS;
        int s1 = c1 < SS ? c1 : SS;
        int s2 = c2 < SS ? c2 : SS;
        int total = c0 + c1 + c2 + c3;
        int eff = total < SS ? total : SS;
        int sel = 0;
        if (eff > 0) {
            int j = tid % eff;
            if (j < s0) sel = buf[0][j];
            else { j -= s0;
                if (j < s1) sel = buf[1][j];
                else { j -= s1;
                    if (j < s2) sel = buf[2][j];
                    else sel = buf[3][j - s2];
                }
            }
        }
        g_sel[q*SS + tid] = sel;
    }
}

// ---------------- time-MLP chain -----------------------------------------------------
__global__ void k_emb(const float* __restrict__ ts) {
    int b = blockIdx.x, tid = threadIdx.x;
    float t = ts[b];
    if (tid < 64) {
        float f = expf(tid * (-9.210340371976184f/63.0f));
        float e = t * f;
        g_e1[b*128 + tid] = sinf(e); g_e1[b*128 + 64 + tid] = cosf(e);
    }
    {
        float f = expf(tid * (-9.210340371976184f/127.0f));
        float e = t * f;
        g_e2[b*256 + tid] = sinf(e); g_e2[b*256 + 128 + tid] = cosf(e);
    }
}

__global__ void k_tstage(const float* __restrict__ WA, const float* __restrict__ bA,
                         const float* __restrict__ WB, const float* __restrict__ bB,
                         int RA, int stage) {
    extern __shared__ float dsm[];
    int blk = blockIdx.x;
    int nA = RA >> 5;
    bool isA = blk < nA;
    const float *W = isA ? WA : WB;
    const float *bias = isA ? bA : bB;
    int row0 = (isA ? blk : blk - nA) << 5;
    const float* gin; float* gout; int K, R; int act;
    if (stage == 0) {
        act = 0;
        if (isA) { gin = g_e1; gout = g_t1; K = 128;  R = 512;  }
        else     { gin = g_e2; gout = g_t2; K = 256;  R = 1024; }
    } else if (stage == 1) {
        act = 1;
        if (isA) { gin = g_t1; gout = g_s1; K = 512;  R = 512;  }
        else     { gin = g_t2; gout = g_s2; K = 1024; R = 1024; }
    } else {
        act = 2;
        if (isA) { gin = g_s1; gout = g_ss;  K = 512;  R = 256; }
        else     { gin = g_s2; gout = g_ss2; K = 1024; R = 512; }
    }
    float* in_s = dsm;
    float* w_s  = dsm + 8 * (K + 4);
    int tid = threadIdx.x;
    int rl = tid >> 3, bb = tid & 7;
    int stride = K + 4;
    int ksh = __ffs(K) - 1;
    for (int i = tid; i < (K << 3); i += 256) {
        int b2 = i >> ksh, c = i & (K - 1);
        in_s[b2 * stride + c] = gin[i];
    }
    float acc = 0.0f;
    for (int ko = 0; ko < K; ko += 128) {
        __syncthreads();
        #pragma unroll
        for (int i = tid; i < 1024; i += 256) {
            int r = i >> 5, c4 = i & 31;
            float4 v = *(const float4*)(W + (size_t)(row0 + r) * K + ko + c4 * 4);
            *(float4*)&w_s[r * 132 + c4 * 4] = v;
        }
        __syncthreads();
        const float* wr = w_s + rl * 132;
        const float* ir = in_s + bb * stride + ko;
        #pragma unroll 8
        for (int c = 0; c < 128; c++) acc += wr[c] * ir[c];
    }
    acc += bias[row0 + rl];
    if (act == 0) acc = gelu_exact(acc);
    else if (act == 1) acc = silu_f(acc);
    gout[bb * R + row0 + rl] = acc;
}

// ---------------- kernel B: 1-proposal point MLP, f32x2 out-pair accumulators -------
// Block = 1 proposal (32 pts) x 128 outs; 256 threads; thread = 2 pts x 8 outs
// (8 b64 accs; each acc = one OUTPUT PAIR for one point -> weights load as natural
// b64 pairs, no packing). smem 52KB -> 4 blocks/SM -> 32 warps/SM.

// layers 1/2: channel-major input [128][HST2]
__device__ __forceinline__ void layerN2(const float* __restrict__ in,
                                        const float* __restrict__ wt,   // [128][128]
                                        const float* __restrict__ bias,
                                        float* __restrict__ out,        // [128][HST2]
                                        int pp, int ohh) {
    ull acc[2][4];
    {
        const ull* bp = (const ull*)(bias + 8*ohh);
        ull b0 = bp[0], b1 = bp[1], b2 = bp[2], b3 = bp[3];
        acc[0][0]=b0; acc[0][1]=b1; acc[0][2]=b2; acc[0][3]=b3;
        acc[1][0]=b0; acc[1][1]=b1; acc[1][2]=b2; acc[1][3]=b3;
    }
    const float* ip = in + 2*pp;
    const float* wp = wt + 8*ohh;
    #pragma unroll 4
    for (int c = 0; c < 128; c++) {
        float2 x = *(const float2*)(ip + c*HST2);
        ull x0 = pack2(x.x), x1 = pack2(x.y);
        ulonglong2 wa = *(const ulonglong2*)(wp + c*128);
        ulonglong2 wb = *(const ulonglong2*)(wp + c*128 + 4);
        FMA_F32X2(acc[0][0], x0, wa.x); FMA_F32X2(acc[1][0], x1, wa.x);
        FMA_F32X2(acc[0][1], x0, wa.y); FMA_F32X2(acc[1][1], x1, wa.y);
        FMA_F32X2(acc[0][2], x0, wb.x); FMA_F32X2(acc[1][2], x1, wb.x);
        FMA_F32X2(acc[0][3], x0, wb.y); FMA_F32X2(acc[1][3], x1, wb.y);
    }
    #pragma unroll
    for (int k = 0; k < 4; k++) {
        #pragma unroll
        for (int i = 0; i < 2; i++) {
            float2 f = unpack2(acc[i][k]);
            out[(8*ohh + 2*k)*HST2     + 2*pp + i] = relu_f(f.x);
            out[(8*ohh + 2*k + 1)*HST2 + 2*pp + i] = relu_f(f.y);
        }
    }
}

// layer 0: point-major swizzled input (256 feature channels + 3 xyz)
__device__ __forceinline__ void layer02(const float* __restrict__ in,   // gpm
                                        const float* __restrict__ wt,   // g_mw0t
                                        const float* __restrict__ bias,
                                        float* __restrict__ out,
                                        int pp, int ohh) {
    ull acc[2][4];
    {
        const ull* bp = (const ull*)(bias + 8*ohh);
        ull b0 = bp[0], b1 = bp[1], b2 = bp[2], b3 = bp[3];
        acc[0][0]=b0; acc[0][1]=b1; acc[0][2]=b2; acc[0][3]=b3;
        acc[1][0]=b0; acc[1][1]=b1; acc[1][2]=b2; acc[1][3]=b3;
    }
    const float* ip0 = in + (2*pp)*STR0;
    const float* ip1 = in + (2*pp + 1)*STR0;
    const float* wp = wt + 8*ohh;
    int key = pp & 7;
    #pragma unroll 4
    for (int c = 0; c < 259; c++) {
        int t = (c < 256) ? ((((c >> 2) ^ key) << 2) | (c & 3)) : c;
        ull x0 = pack2(ip0[t]), x1 = pack2(ip1[t]);
        ulonglong2 wa = *(const ulonglong2*)(wp + c*128);
        ulonglong2 wb = *(const ulonglong2*)(wp + c*128 + 4);
        FMA_F32X2(acc[0][0], x0, wa.x); FMA_F32X2(acc[1][0], x1, wa.x);
        FMA_F32X2(acc[0][1], x0, wa.y); FMA_F32X2(acc[1][1], x1, wa.y);
        FMA_F32X2(acc[0][2], x0, wb.x); FMA_F32X2(acc[1][2], x1, wb.x);
        FMA_F32X2(acc[0][3], x0, wb.y); FMA_F32X2(acc[1][3], x1, wb.y);
    }
    #pragma unroll
    for (int k = 0; k < 4; k++) {
        #pragma unroll
        for (int i = 0; i < 2; i++) {
            float2 f = unpack2(acc[i][k]);
            out[(8*ohh + 2*k)*HST2     + 2*pp + i] = relu_f(f.x);
            out[(8*ohh + 2*k + 1)*HST2 + 2*pp + i] = relu_f(f.y);
        }
    }
}

__global__ void __launch_bounds__(256, 4) k_mlp(
                      const float* __restrict__ xyz,
                      const int* __restrict__ inds,
                      const float* __restrict__ mb0, const float* __restrict__ mb1,
                      const float* __restrict__ mb2) {
    extern __shared__ float sm[];
    float* gpm = sm;                    // [32][STR0] gather; reused as hB [128][HST2]
    float* hA  = sm + 32*STR0;          // [128][HST2]
    __shared__ int   sidx[32];
    __shared__ float ctr[3];

    int q = blockIdx.x, b = q >> 8;
    int tid = threadIdx.x;              // 256 threads
    if (tid < 32) sidx[tid] = g_sel[q*SS + tid];
    if (tid < 3) ctr[tid] = xyz[((size_t)b*NN + inds[q])*3 + tid];
    __syncthreads();

    // gather: 32 points x 64 float4 chunks, coalesced rows; swizzle key (s>>1)&7
    const float* ftb = g_ft + (size_t)b * NN * CC;
    #pragma unroll
    for (int i = tid; i < 32*64; i += 256) {
        int s = i >> 6, c4 = i & 63;
        float4 v = *(const float4*)(ftb + (size_t)sidx[s]*CC + (c4 << 2));
        int cc = (c4 & ~7) | ((c4 ^ (s >> 1)) & 7);
        *(float4*)(gpm + s*STR0 + (cc << 2)) = v;
    }
    if (tid < 32) {
        const float* p = xyz + ((size_t)b*NN + sidx[tid])*3;
        #pragma unroll
        for (int d = 0; d < 3; d++)
            gpm[tid*STR0 + 256 + d] = p[d] - ctr[d];
    }
    __syncthreads();

    int pp = tid & 15, ohh = tid >> 4;   // pp: point pair, ohh: 8-out group
    layer02(gpm, g_mw0t, mb0, hA, pp, ohh);   __syncthreads();
    layerN2(hA, g_mw1t, mb1, gpm, pp, ohh);   __syncthreads();
    layerN2(gpm, g_mw2t, mb2, hA, pp, ohh);   __syncthreads();

    // maxpool over 32 samples (relu outputs >= 0)
    if (tid < 128) {
        const float* r = hA + tid*HST2;
        float m = 0.0f;
        #pragma unroll
        for (int j = 0; j < 32; j += 4) {
            float4 v = *(const float4*)(r + j);
            m = fmaxf(m, fmaxf(fmaxf(v.x, v.y), fmaxf(v.z, v.w)));
        }
        g_nf[q*128 + tid] = m;
    }
}

// ---------------- kernel C: label MLP, 4 proposals/block ----------------------------
__global__ void __launch_bounds__(256) k_label(const float* __restrict__ blabel,
                       const float* __restrict__ lb0, const float* __restrict__ lb1,
                       const float* __restrict__ lb2) {
    __shared__ float in0[4][152];
    __shared__ float h1[4][256];
    __shared__ float h2[4][256];
    int q0 = blockIdx.x * 4;
    int tid = threadIdx.x;               // 256 threads = 256 outputs
    if (tid < 4*NCC) {
        int j = tid / NCC, c = tid - j*NCC;
        in0[j][c] = blabel[(q0 + j)*NCC + c];
    }
    #pragma unroll
    for (int i = tid; i < 512; i += 256) {
        int j = i >> 7, c = i & 127;
        in0[j][NCC + c] = g_nf[(q0 + j)*128 + c];
    }
    __syncthreads();
    int o = tid;
    float a0 = lb0[o], a1 = a0, a2 = a0, a3 = a0;
    #pragma unroll 2
    for (int c = 0; c < 146; c++) {
        float w = g_lw0t[c*256 + o];
        a0 += in0[0][c]*w; a1 += in0[1][c]*w; a2 += in0[2][c]*w; a3 += in0[3][c]*w;
    }
    h1[0][o] = relu_f(a0); h1[1][o] = relu_f(a1);
    h1[2][o] = relu_f(a2); h1[3][o] = relu_f(a3);
    __syncthreads();
    a0 = lb1[o]; a1 = a0; a2 = a0; a3 = a0;
    #pragma unroll 4
    for (int c = 0; c < 256; c++) {
        float w = g_lw1t[c*256 + o];
        a0 += h1[0][c]*w; a1 += h1[1][c]*w; a2 += h1[2][c]*w; a3 += h1[3][c]*w;
    }
    h2[0][o] = relu_f(a0); h2[1][o] = relu_f(a1);
    h2[2][o] = relu_f(a2); h2[3][o] = relu_f(a3);
    __syncthreads();
    a0 = lb2[o]; a1 = a0; a2 = a0; a3 = a0;
    #pragma unroll 4
    for (int c = 0; c < 256; c++) {
        float w = g_lw2t[c*256 + o];
        a0 += h2[0][c]*w; a1 += h2[1][c]*w; a2 += h2[2][c]*w; a3 += h2[3][c]*w;
    }
    g_lf[(q0+0)*256 + o] = relu_f(a0);
    g_lf[(q0+1)*256 + o] = relu_f(a1);
    g_lf[(q0+2)*256 + o] = relu_f(a2);
    g_lf[(q0+3)*256 + o] = relu_f(a3);
}

// ---------------- kernel D: FiLM + all outputs ---------------------------------------
__global__ void k_out(float* __restrict__ out, const float* __restrict__ xyz,
                      const int* __restrict__ inds) {
    const int O0 = BB*PP*3;
    const int O1 = O0 + BB*128*PP;
    const int O2 = O1 + BB*256*PP;
    const int O3 = O2 + BB*PP;
    int i = blockIdx.x * blockDim.x + threadIdx.x;
    if (i < O0) {
        int b = i / (PP*3); int r = i - b*(PP*3); int p = r/3, d = r - p*3;
        out[i] = xyz[((size_t)b*NN + inds[b*PP + p])*3 + d];
    } else if (i < O1) {
        int j = i - O0;
        int b = j >> 15;
        int r = j & 32767;
        int d = r >> 8, p = r & 255;
        int m = p & 127;
        out[i] = g_nf[((b<<8) + p)*128 + d] * (g_ss[b*256 + m] + 1.0f)
               + g_ss[b*256 + 128 + m];
    } else if (i < O2) {
        int j = i - O1;
        int b = j >> 16;
        int r = j & 65535;
        int d = r >> 8, p = r & 255;
        out[i] = g_lf[((b<<8) + p)*256 + d] * (g_ss2[b*512 + p] + 1.0f)
               + g_ss2[b*512 + 256 + p];
    } else if (i < O3) {
        out[i] = (float)inds[i - O2];
    }
}

// ---------------- launcher -----------------------------------------------------------
extern "C" void kernel_launch(void* const* d_in, const int* in_sizes, int n_in,
                              void* d_out, int out_size) {
    const float* xyz    = (const float*)d_in[0];
    const float* feat   = (const float*)d_in[1];
    const float* bsize  = (const float*)d_in[2];
    const float* blabel = (const float*)d_in[3];
    const float* ts     = (const float*)d_in[4];
    const int*   inds   = (const int*)  d_in[5];
    const float* mw0 = (const float*)d_in[6],  *mb0 = (const float*)d_in[7];
    const float* mw1 = (const float*)d_in[8],  *mb1 = (const float*)d_in[9];
    const float* mw2 = (const float*)d_in[10], *mb2 = (const float*)d_in[11];
    const float* lw0 = (const float*)d_in[12], *lb0 = (const float*)d_in[13];
    const float* lw1 = (const float*)d_in[14], *lb1 = (const float*)d_in[15];
    const float* lw2 = (const float*)d_in[16], *lb2 = (const float*)d_in[17];
    const float* tw0 = (const float*)d_in[18], *tb0 = (const float*)d_in[19];
    const float* tw1 = (const float*)d_in[20], *tb1 = (const float*)d_in[21];
    const float* bw  = (const float*)d_in[22], *bbv = (const float*)d_in[23];
    const float* tlw0= (const float*)d_in[24], *tlb0= (const float*)d_in[25];
    const float* tlw1= (const float*)d_in[26], *tlb1= (const float*)d_in[27];
    const float* blw = (const float*)d_in[28], *blb = (const float*)d_in[29];
    float* out = (float*)d_out;

    dim3 tb(32, 8);
    k_prep<<<876, tb>>>(xyz, mw0, mw1, mw2, lw0, lw1, lw2);          // 0
    k_sample<<<BP, 128>>>(xyz, bsize, inds);                         // 1
    k_ftrans<<<dim3(625, 8, 8), tb>>>(feat);                         // 2

    int smem_b = (32*STR0 + 128*HST2) * (int)sizeof(float);          // 52224 B
    cudaFuncSetAttribute(k_mlp, cudaFuncAttributeMaxDynamicSharedMemorySize, smem_b);
    k_mlp<<<BP, 256, smem_b>>>(xyz, inds, mb0, mb1, mb2);            // 3 <- profiled

    k_label<<<BP/4, 256>>>(blabel, lb0, lb1, lb2);                   // 4
    k_emb<<<BB, 128>>>(ts);                                          // 5
    int smem_t = (8*(1024+4) + 32*132) * (int)sizeof(float);         // 49792 B
    cudaFuncSetAttribute(k_tstage, cudaFuncAttributeMaxDynamicSharedMemorySize, smem_t);
    k_tstage<<<48, 256, smem_t>>>(tw0, tb0, tlw0, tlb0, 512, 0);     // 6
    k_tstage<<<48, 256, smem_t>>>(tw1, tb1, tlw1, tlb1, 512, 1);     // 7
    k_tstage<<<24, 256, smem_t>>>(bw,  bbv, blw,  blb,  256, 2);     // 8

    const int total = BB*PP*3 + BB*128*PP + BB*256*PP + BB*PP;       // 794624
    k_out<<<(total + 255)/256, 256>>>(out, xyz, inds);               // 9
}

// round 16
// speedup vs baseline: 1.4709x; 1.2151x over previous
#include <cuda_runtime.h>
#include <math.h>

// Problem constants
#define BB   8
#define NN   20000
#define NPAD 20480        // 160 * 128
#define QTR  (NPAD/4)
#define PP   256
#define SS   32
#define CC   256
#define NCC  18
#define BP   (BB*PP)      // 2048
#define STR0 264          // point-major gather row stride (floats)
#define HST2 36           // channel-major hidden row stride (32 pts + 4 pad)

typedef unsigned long long ull;

// packed f32x2 helpers (sm_103a)
#define FMA_F32X2(a, x, w) \
    asm("fma.rn.f32x2 %0, %1, %2, %0;" : "+l"(a) : "l"(x), "l"(w))
__device__ __forceinline__ ull pack2(float v) {
    ull r; asm("mov.b64 %0, {%1, %1};" : "=l"(r) : "f"(v)); return r;
}
__device__ __forceinline__ float2 unpack2(ull a) {
    float2 f; asm("mov.b64 {%0, %1}, %2;" : "=f"(f.x), "=f"(f.y) : "l"(a)); return f;
}

// ---------------- scratch (__device__ globals; no allocation allowed) ---------------
// NOTE: never pass these as kernel arguments from host code (ATS hides the bug).
__device__ int   g_sel[BP*SS];
__device__ float g_nf [BP*128];
__device__ float g_lf [BP*256];
__device__ float g_ss [BB*256];
__device__ float g_ss2[BB*512];
__device__ __align__(16) float g_sx[BB*NPAD];
__device__ __align__(16) float g_sy[BB*NPAD];
__device__ __align__(16) float g_sz[BB*NPAD];
__device__ __align__(16) float g_ft[(size_t)BB*NN*CC];   // features transposed [b][n][c]
__device__ float g_e1[BB*128], g_e2[BB*256];
__device__ float g_t1[BB*512], g_t2[BB*1024];
__device__ float g_s1[BB*512], g_s2[BB*1024];

// transposed weights [K][O]; g_mw0t rows permuted: c<256 = feature c, 256..258 = xyz
__device__ __align__(16) float g_mw0t [259*128];
__device__ __align__(16) float g_mw1t [128*128];
__device__ __align__(16) float g_mw2t [128*128];
__device__ __align__(16) float g_lw0t [146*256];
__device__ __align__(16) float g_lw1t [256*256];
__device__ __align__(16) float g_lw2t [256*256];

__device__ __forceinline__ float gelu_exact(float x) {
    return 0.5f * x * (1.0f + erff(x * 0.70710678118654752f));
}
__device__ __forceinline__ float silu_f(float x) { return x / (1.0f + expf(-x)); }
__device__ __forceinline__ float relu_f(float x) { return fmaxf(x, 0.0f); }

// ---------------- kernel P: fused prep = xyz SoA + 6 weight transposes --------------
__global__ void k_prep(const float* __restrict__ xyz,
                       const float* __restrict__ mw0, const float* __restrict__ mw1,
                       const float* __restrict__ mw2, const float* __restrict__ lw0,
                       const float* __restrict__ lw1, const float* __restrict__ lw2) {
    int blk = blockIdx.x;
    int tx = threadIdx.x, ty = threadIdx.y;
    int tid = ty * 32 + tx;
    if (blk < 640) {
        int i = blk * 256 + tid;
        if (i >= BB * NPAD) return;
        int b = i / NPAD, n = i - b * NPAD;
        float x = 3e38f, y = 3e38f, z = 3e38f;
        if (n < NN) {
            const float* p = xyz + ((size_t)b * NN + n) * 3;
            x = p[0]; y = p[1]; z = p[2];
        }
        g_sx[i] = x; g_sy[i] = y; g_sz[i] = z;
        return;
    }
    int t = blk - 640;
    const float* src; float* dst; int O, K, base; bool perm = false;
    if      (t < 36)  { src = mw0; dst = g_mw0t; O = 128; K = 259; base = 0;   perm = true; }
    else if (t < 52)  { src = mw1; dst = g_mw1t; O = 128; K = 128; base = 36;  }
    else if (t < 68)  { src = mw2; dst = g_mw2t; O = 128; K = 128; base = 52;  }
    else if (t < 108) { src = lw0; dst = g_lw0t; O = 256; K = 146; base = 68;  }
    else if (t < 172) { src = lw1; dst = g_lw1t; O = 256; K = 256; base = 108; }
    else              { src = lw2; dst = g_lw2t; O = 256; K = 256; base = 172; }
    int tile = t - base;
    int ntk = (K + 31) >> 5;
    int kt = tile % ntk, ot = tile / ntk;
    __shared__ float s[32][33];
    int k0 = kt * 32, o0 = ot * 32;
    #pragma unroll
    for (int i = ty; i < 32; i += 8) {
        int o = o0 + i, k = k0 + tx;
        if (o < O && k < K) {
            int sk = perm ? (k < 256 ? k + 3 : k - 256) : k;
            s[i][tx] = src[o * K + sk];
        }
    }
    __syncthreads();
    #pragma unroll
    for (int i = ty; i < 32; i += 8) {
        int k = k0 + i, o = o0 + tx;
        if (k < K && o < O) dst[k * O + o] = s[tx][i];
    }
}

// ---------------- kernel F: feature transpose [C][N] -> [N][C] ----------------------
__global__ void k_ftrans(const float* __restrict__ feat) {
    __shared__ float t[32][33];
    int tx = threadIdx.x, ty = threadIdx.y;
    int n0 = blockIdx.x << 5, c0 = blockIdx.y << 5, b = blockIdx.z;
    const float* src = feat + ((size_t)(b * CC + c0)) * NN + n0;
    #pragma unroll
    for (int i = ty; i < 32; i += 8)
        t[i][tx] = src[(size_t)i * NN + tx];
    __syncthreads();
    float* dst = g_ft + ((size_t)b * NN + n0) * CC + c0;
    #pragma unroll
    for (int i = ty; i < 32; i += 8)
        dst[(size_t)i * CC + tx] = t[tx][i];
}

// ---------------- kernel A: in-box sampling, 4 warps/proposal quarter-scan + merge --
__global__ void __launch_bounds__(128) k_sample(const float* __restrict__ xyz,
                         const float* __restrict__ bsize,
                         const int*   __restrict__ inds) {
    __shared__ int buf[4][SS];
    __shared__ int cnt[4];
    int tid = threadIdx.x;
    int lane = tid & 31, w = tid >> 5;
    int q = blockIdx.x;
    int b = q >> 8;
    int n0 = inds[q];
    const float* cp = xyz + ((size_t)b * NN + n0) * 3;
    float cx = cp[0], cy = cp[1], cz = cp[2];
    float hx = bsize[q*3+0]*0.5f, hy = bsize[q*3+1]*0.5f, hz = bsize[q*3+2]*0.5f;
    const float4* X = (const float4*)(g_sx + b * NPAD);
    const float4* Y = (const float4*)(g_sy + b * NPAD);
    const float4* Z = (const float4*)(g_sz + b * NPAD);

    int vbase = w * (QTR/4);
    unsigned below = (1u << lane) - 1u;
    int found = 0;
    float4 xs = X[vbase + lane], ys = Y[vbase + lane], zs = Z[vbase + lane];
    const int ITERS = QTR / 128;                   // 40
    for (int it = 0; it < ITERS; it++) {
        float4 nx, ny, nz;
        if (it + 1 < ITERS) {
            int v = vbase + (it + 1) * 32 + lane;
            nx = X[v]; ny = Y[v]; nz = Z[v];
        }
        bool i0 = (fabsf(xs.x-cx)<=hx) && (fabsf(ys.x-cy)<=hy) && (fabsf(zs.x-cz)<=hz);
        bool i1 = (fabsf(xs.y-cx)<=hx) && (fabsf(ys.y-cy)<=hy) && (fabsf(zs.y-cz)<=hz);
        bool i2 = (fabsf(xs.z-cx)<=hx) && (fabsf(ys.z-cy)<=hy) && (fabsf(zs.z-cz)<=hz);
        bool i3 = (fabsf(xs.w-cx)<=hx) && (fabsf(ys.w-cy)<=hy) && (fabsf(zs.w-cz)<=hz);
        unsigned m0 = __ballot_sync(0xffffffffu, i0);
        unsigned m1 = __ballot_sync(0xffffffffu, i1);
        unsigned m2 = __ballot_sync(0xffffffffu, i2);
        unsigned m3 = __ballot_sync(0xffffffffu, i3);
        if (m0 | m1 | m2 | m3) {
            int pre = found
                    + __popc(m0 & below) + __popc(m1 & below)
                    + __popc(m2 & below) + __popc(m3 & below);
            int np = w * QTR + it * 128 + 4 * lane;
            unsigned b0 = (m0 >> lane) & 1u, b1 = (m1 >> lane) & 1u, b2 = (m2 >> lane) & 1u;
            if (i0 && pre < SS)                    buf[w][pre] = np;
            int r1 = pre + (int)b0;
            if (i1 && r1 < SS)                     buf[w][r1] = np + 1;
            int r2 = r1 + (int)b1;
            if (i2 && r2 < SS)                     buf[w][r2] = np + 2;
            int r3 = r2 + (int)b2;
            if (i3 && r3 < SS)                     buf[w][r3] = np + 3;
        }
        found += __popc(m0) + __popc(m1) + __popc(m2) + __popc(m3);
        if (found >= SS) break;
        xs = nx; ys = ny; zs = nz;
    }
    if (lane == 0) cnt[w] = found;
    __syncthreads();

    if (tid < 32) {
        int c0 = cnt[0], c1 = cnt[1], c2 = cnt[2], c3 = cnt[3];
        int s0 = c0 < SS ? c0 : SS;
        int s1 = c1 < SS ? c1 : SS;
        int s2 = c2 < SS ? c2 : SS;
        int total = c0 + c1 + c2 + c3;
        int eff = total < SS ? total : SS;
        int sel = 0;
        if (eff > 0) {
            int j = tid % eff;
            if (j < s0) sel = buf[0][j];
            else { j -= s0;
                if (j < s1) sel = buf[1][j];
                else { j -= s1;
                    if (j < s2) sel = buf[2][j];
                    else sel = buf[3][j - s2];
                }
            }
        }
        g_sel[q*SS + tid] = sel;
    }
}

// ---------------- time-MLP chain -----------------------------------------------------
__global__ void k_emb(const float* __restrict__ ts) {
    int b = blockIdx.x, tid = threadIdx.x;
    float t = ts[b];
    if (tid < 64) {
        float f = expf(tid * (-9.210340371976184f/63.0f));
        float e = t * f;
        g_e1[b*128 + tid] = sinf(e); g_e1[b*128 + 64 + tid] = cosf(e);
    }
    {
        float f = expf(tid * (-9.210340371976184f/127.0f));
        float e = t * f;
        g_e2[b*256 + tid] = sinf(e); g_e2[b*256 + 128 + tid] = cosf(e);
    }
}

__global__ void k_tstage(const float* __restrict__ WA, const float* __restrict__ bA,
                         const float* __restrict__ WB, const float* __restrict__ bB,
                         int RA, int stage) {
    extern __shared__ float dsm[];
    int blk = blockIdx.x;
    int nA = RA >> 5;
    bool isA = blk < nA;
    const float *W = isA ? WA : WB;
    const float *bias = isA ? bA : bB;
    int row0 = (isA ? blk : blk - nA) << 5;
    const float* gin; float* gout; int K, R; int act;
    if (stage == 0) {
        act = 0;
        if (isA) { gin = g_e1; gout = g_t1; K = 128;  R = 512;  }
        else     { gin = g_e2; gout = g_t2; K = 256;  R = 1024; }
    } else if (stage == 1) {
        act = 1;
        if (isA) { gin = g_t1; gout = g_s1; K = 512;  R = 512;  }
        else     { gin = g_t2; gout = g_s2; K = 1024; R = 1024; }
    } else {
        act = 2;
        if (isA) { gin = g_s1; gout = g_ss;  K = 512;  R = 256; }
        else     { gin = g_s2; gout = g_ss2; K = 1024; R = 512; }
    }
    float* in_s = dsm;
    float* w_s  = dsm + 8 * (K + 4);
    int tid = threadIdx.x;
    int rl = tid >> 3, bb = tid & 7;
    int stride = K + 4;
    int ksh = __ffs(K) - 1;
    for (int i = tid; i < (K << 3); i += 256) {
        int b2 = i >> ksh, c = i & (K - 1);
        in_s[b2 * stride + c] = gin[i];
    }
    float acc = 0.0f;
    for (int ko = 0; ko < K; ko += 128) {
        __syncthreads();
        #pragma unroll
        for (int i = tid; i < 1024; i += 256) {
            int r = i >> 5, c4 = i & 31;
            float4 v = *(const float4*)(W + (size_t)(row0 + r) * K + ko + c4 * 4);
            *(float4*)&w_s[r * 132 + c4 * 4] = v;
        }
        __syncthreads();
        const float* wr = w_s + rl * 132;
        const float* ir = in_s + bb * stride + ko;
        #pragma unroll 8
        for (int c = 0; c < 128; c++) acc += wr[c] * ir[c];
    }
    acc += bias[row0 + rl];
    if (act == 0) acc = gelu_exact(acc);
    else if (act == 1) acc = silu_f(acc);
    gout[bb * R + row0 + rl] = acc;
}

// ---------------- kernel B: 1-proposal point MLP, 4pts x 8outs f32x2 ----------------
// Block = 1 proposal (32 pts) x 128 outs; 128 threads; thread = 4 pts x 8 outs
// (16 b64 accs = out-pairs). Per c: 1 LDS.128 (or 4 scalar LDS layer0) + 2 LDG.128
// + 16 FFMA2 -> L1 wavefronts per FLOP halved vs 2pt tile.

// layers 1/2: channel-major input [128][HST2]; pg in [0,8), ohh in [0,16)
__device__ __forceinline__ void layerN4(const float* __restrict__ in,
                                        const float* __restrict__ wt,   // [128][128]
                                        const float* __restrict__ bias,
                                        float* __restrict__ out,        // [128][HST2]
                                        int pg, int ohh) {
    ull acc[4][4];
    {
        const ull* bp = (const ull*)(bias + 8*ohh);
        ull b0 = bp[0], b1 = bp[1], b2 = bp[2], b3 = bp[3];
        #pragma unroll
        for (int j = 0; j < 4; j++) {
            acc[j][0] = b0; acc[j][1] = b1; acc[j][2] = b2; acc[j][3] = b3;
        }
    }
    const float* ip = in + 4*pg;
    const float* wp = wt + 8*ohh;
    #pragma unroll 4
    for (int c = 0; c < 128; c++) {
        float4 x = *(const float4*)(ip + c*HST2);
        ull x0 = pack2(x.x), x1 = pack2(x.y), x2 = pack2(x.z), x3 = pack2(x.w);
        ulonglong2 wa = *(const ulonglong2*)(wp + c*128);
        ulonglong2 wb = *(const ulonglong2*)(wp + c*128 + 4);
        FMA_F32X2(acc[0][0], x0, wa.x); FMA_F32X2(acc[1][0], x1, wa.x);
        FMA_F32X2(acc[2][0], x2, wa.x); FMA_F32X2(acc[3][0], x3, wa.x);
        FMA_F32X2(acc[0][1], x0, wa.y); FMA_F32X2(acc[1][1], x1, wa.y);
        FMA_F32X2(acc[2][1], x2, wa.y); FMA_F32X2(acc[3][1], x3, wa.y);
        FMA_F32X2(acc[0][2], x0, wb.x); FMA_F32X2(acc[1][2], x1, wb.x);
        FMA_F32X2(acc[2][2], x2, wb.x); FMA_F32X2(acc[3][2], x3, wb.x);
        FMA_F32X2(acc[0][3], x0, wb.y); FMA_F32X2(acc[1][3], x1, wb.y);
        FMA_F32X2(acc[2][3], x2, wb.y); FMA_F32X2(acc[3][3], x3, wb.y);
    }
    #pragma unroll
    for (int k = 0; k < 4; k++) {
        float2 f0 = unpack2(acc[0][k]);
        float2 f1 = unpack2(acc[1][k]);
        float2 f2 = unpack2(acc[2][k]);
        float2 f3 = unpack2(acc[3][k]);
        *(float4*)(out + (8*ohh + 2*k)*HST2 + 4*pg) =
            make_float4(relu_f(f0.x), relu_f(f1.x), relu_f(f2.x), relu_f(f3.x));
        *(float4*)(out + (8*ohh + 2*k + 1)*HST2 + 4*pg) =
            make_float4(relu_f(f0.y), relu_f(f1.y), relu_f(f2.y), relu_f(f3.y));
    }
}

// layer 0: point-major swizzled input (256 feature channels + 3 xyz)
__device__ __forceinline__ void layer04(const float* __restrict__ in,   // gpm
                                        const float* __restrict__ wt,   // g_mw0t
                                        const float* __restrict__ bias,
                                        float* __restrict__ out,
                                        int pg, int ohh) {
    ull acc[4][4];
    {
        const ull* bp = (const ull*)(bias + 8*ohh);
        ull b0 = bp[0], b1 = bp[1], b2 = bp[2], b3 = bp[3];
        #pragma unroll
        for (int j = 0; j < 4; j++) {
            acc[j][0] = b0; acc[j][1] = b1; acc[j][2] = b2; acc[j][3] = b3;
        }
    }
    const float* ip0 = in + (4*pg + 0)*STR0;
    const float* ip1 = in + (4*pg + 1)*STR0;
    const float* ip2 = in + (4*pg + 2)*STR0;
    const float* ip3 = in + (4*pg + 3)*STR0;
    const float* wp = wt + 8*ohh;
    #pragma unroll 4
    for (int c = 0; c < 259; c++) {
        // gather swizzle key = (s>>2) = pg for these 4 rows
        int t = (c < 256) ? ((((c >> 2) ^ pg) << 2) | (c & 3)) : c;
        ull x0 = pack2(ip0[t]), x1 = pack2(ip1[t]);
        ull x2 = pack2(ip2[t]), x3 = pack2(ip3[t]);
        ulonglong2 wa = *(const ulonglong2*)(wp + c*128);
        ulonglong2 wb = *(const ulonglong2*)(wp + c*128 + 4);
        FMA_F32X2(acc[0][0], x0, wa.x); FMA_F32X2(acc[1][0], x1, wa.x);
        FMA_F32X2(acc[2][0], x2, wa.x); FMA_F32X2(acc[3][0], x3, wa.x);
        FMA_F32X2(acc[0][1], x0, wa.y); FMA_F32X2(acc[1][1], x1, wa.y);
        FMA_F32X2(acc[2][1], x2, wa.y); FMA_F32X2(acc[3][1], x3, wa.y);
        FMA_F32X2(acc[0][2], x0, wb.x); FMA_F32X2(acc[1][2], x1, wb.x);
        FMA_F32X2(acc[2][2], x2, wb.x); FMA_F32X2(acc[3][2], x3, wb.x);
        FMA_F32X2(acc[0][3], x0, wb.y); FMA_F32X2(acc[1][3], x1, wb.y);
        FMA_F32X2(acc[2][3], x2, wb.y); FMA_F32X2(acc[3][3], x3, wb.y);
    }
    #pragma unroll
    for (int k = 0; k < 4; k++) {
        float2 f0 = unpack2(acc[0][k]);
        float2 f1 = unpack2(acc[1][k]);
        float2 f2 = unpack2(acc[2][k]);
        float2 f3 = unpack2(acc[3][k]);
        *(float4*)(out + (8*ohh + 2*k)*HST2 + 4*pg) =
            make_float4(relu_f(f0.x), relu_f(f1.x), relu_f(f2.x), relu_f(f3.x));
        *(float4*)(out + (8*ohh + 2*k + 1)*HST2 + 4*pg) =
            make_float4(relu_f(f0.y), relu_f(f1.y), relu_f(f2.y), relu_f(f3.y));
    }
}

__global__ void __launch_bounds__(128, 4) k_mlp(
                      const float* __restrict__ xyz,
                      const int* __restrict__ inds,
                      const float* __restrict__ mb0, const float* __restrict__ mb1,
                      const float* __restrict__ mb2) {
    extern __shared__ float sm[];
    float* gpm = sm;                    // [32][STR0] gather; reused as hB [128][HST2]
    float* hA  = sm + 32*STR0;          // [128][HST2]
    __shared__ int   sidx[32];
    __shared__ float ctr[3];

    int q = blockIdx.x, b = q >> 8;
    int tid = threadIdx.x;              // 128 threads
    if (tid < 32) sidx[tid] = g_sel[q*SS + tid];
    if (tid < 3) ctr[tid] = xyz[((size_t)b*NN + inds[q])*3 + tid];
    __syncthreads();

    // gather: 32 points x 64 float4 chunks, coalesced rows; swizzle key (s>>2)&7
    const float* ftb = g_ft + (size_t)b * NN * CC;
    #pragma unroll
    for (int i = tid; i < 32*64; i += 128) {
        int s = i >> 6, c4 = i & 63;
        float4 v = *(const float4*)(ftb + (size_t)sidx[s]*CC + (c4 << 2));
        int cc = (c4 & ~7) | ((c4 ^ (s >> 2)) & 7);
        *(float4*)(gpm + s*STR0 + (cc << 2)) = v;
    }
    if (tid < 32) {
        const float* p = xyz + ((size_t)b*NN + sidx[tid])*3;
        #pragma unroll
        for (int d = 0; d < 3; d++)
            gpm[tid*STR0 + 256 + d] = p[d] - ctr[d];
    }
    __syncthreads();

    int pg = tid & 7, ohh = tid >> 3;    // pg: 4-point group, ohh: 8-out group
    layer04(gpm, g_mw0t, mb0, hA, pg, ohh);   __syncthreads();
    layerN4(hA, g_mw1t, mb1, gpm, pg, ohh);   __syncthreads();
    layerN4(gpm, g_mw2t, mb2, hA, pg, ohh);   __syncthreads();

    // maxpool over 32 samples (relu outputs >= 0); 128 threads = 128 channels
    {
        const float* r = hA + tid*HST2;
        float m = 0.0f;
        #pragma unroll
        for (int j = 0; j < 32; j += 4) {
            float4 v = *(const float4*)(r + j);
            m = fmaxf(m, fmaxf(fmaxf(v.x, v.y), fmaxf(v.z, v.w)));
        }
        g_nf[q*128 + tid] = m;
    }
}

// ---------------- kernel C: label MLP, 4 proposals/block ----------------------------
__global__ void __launch_bounds__(256) k_label(const float* __restrict__ blabel,
                       const float* __restrict__ lb0, const float* __restrict__ lb1,
                       const float* __restrict__ lb2) {
    __shared__ float in0[4][152];
    __shared__ float h1[4][256];
    __shared__ float h2[4][256];
    int q0 = blockIdx.x * 4;
    int tid = threadIdx.x;               // 256 threads = 256 outputs
    if (tid < 4*NCC) {
        int j = tid / NCC, c = tid - j*NCC;
        in0[j][c] = blabel[(q0 + j)*NCC + c];
    }
    #pragma unroll
    for (int i = tid; i < 512; i += 256) {
        int j = i >> 7, c = i & 127;
        in0[j][NCC + c] = g_nf[(q0 + j)*128 + c];
    }
    __syncthreads();
    int o = tid;
    float a0 = lb0[o], a1 = a0, a2 = a0, a3 = a0;
    #pragma unroll 2
    for (int c = 0; c < 146; c++) {
        float w = g_lw0t[c*256 + o];
        a0 += in0[0][c]*w; a1 += in0[1][c]*w; a2 += in0[2][c]*w; a3 += in0[3][c]*w;
    }
    h1[0][o] = relu_f(a0); h1[1][o] = relu_f(a1);
    h1[2][o] = relu_f(a2); h1[3][o] = relu_f(a3);
    __syncthreads();
    a0 = lb1[o]; a1 = a0; a2 = a0; a3 = a0;
    #pragma unroll 4
    for (int c = 0; c < 256; c++) {
        float w = g_lw1t[c*256 + o];
        a0 += h1[0][c]*w; a1 += h1[1][c]*w; a2 += h1[2][c]*w; a3 += h1[3][c]*w;
    }
    h2[0][o] = relu_f(a0); h2[1][o] = relu_f(a1);
    h2[2][o] = relu_f(a2); h2[3][o] = relu_f(a3);
    __syncthreads();
    a0 = lb2[o]; a1 = a0; a2 = a0; a3 = a0;
    #pragma unroll 4
    for (int c = 0; c < 256; c++) {
        float w = g_lw2t[c*256 + o];
        a0 += h2[0][c]*w; a1 += h2[1][c]*w; a2 += h2[2][c]*w; a3 += h2[3][c]*w;
    }
    g_lf[(q0+0)*256 + o] = relu_f(a0);
    g_lf[(q0+1)*256 + o] = relu_f(a1);
    g_lf[(q0+2)*256 + o] = relu_f(a2);
    g_lf[(q0+3)*256 + o] = relu_f(a3);
}

// ---------------- kernel D: FiLM + all outputs ---------------------------------------
__global__ void k_out(float* __restrict__ out, const float* __restrict__ xyz,
                      const int* __restrict__ inds) {
    const int O0 = BB*PP*3;
    const int O1 = O0 + BB*128*PP;
    const int O2 = O1 + BB*256*PP;
    const int O3 = O2 + BB*PP;
    int i = blockIdx.x * blockDim.x + threadIdx.x;
    if (i < O0) {
        int b = i / (PP*3); int r = i - b*(PP*3); int p = r/3, d = r - p*3;
        out[i] = xyz[((size_t)b*NN + inds[b*PP + p])*3 + d];
    } else if (i < O1) {
        int j = i - O0;
        int b = j >> 15;
        int r = j & 32767;
        int d = r >> 8, p = r & 255;
        int m = p & 127;
        out[i] = g_nf[((b<<8) + p)*128 + d] * (g_ss[b*256 + m] + 1.0f)
               + g_ss[b*256 + 128 + m];
    } else if (i < O2) {
        int j = i - O1;
        int b = j >> 16;
        int r = j & 65535;
        int d = r >> 8, p = r & 255;
        out[i] = g_lf[((b<<8) + p)*256 + d] * (g_ss2[b*512 + p] + 1.0f)
               + g_ss2[b*512 + 256 + p];
    } else if (i < O3) {
        out[i] = (float)inds[i - O2];
    }
}

// ---------------- launcher -----------------------------------------------------------
extern "C" void kernel_launch(void* const* d_in, const int* in_sizes, int n_in,
                              void* d_out, int out_size) {
    const float* xyz    = (const float*)d_in[0];
    const float* feat   = (const float*)d_in[1];
    const float* bsize  = (const float*)d_in[2];
    const float* blabel = (const float*)d_in[3];
    const float* ts     = (const float*)d_in[4];
    const int*   inds   = (const int*)  d_in[5];
    const float* mw0 = (const float*)d_in[6],  *mb0 = (const float*)d_in[7];
    const float* mw1 = (const float*)d_in[8],  *mb1 = (const float*)d_in[9];
    const float* mw2 = (const float*)d_in[10], *mb2 = (const float*)d_in[11];
    const float* lw0 = (const float*)d_in[12], *lb0 = (const float*)d_in[13];
    const float* lw1 = (const float*)d_in[14], *lb1 = (const float*)d_in[15];
    const float* lw2 = (const float*)d_in[16], *lb2 = (const float*)d_in[17];
    const float* tw0 = (const float*)d_in[18], *tb0 = (const float*)d_in[19];
    const float* tw1 = (const float*)d_in[20], *tb1 = (const float*)d_in[21];
    const float* bw  = (const float*)d_in[22], *bbv = (const float*)d_in[23];
    const float* tlw0= (const float*)d_in[24], *tlb0= (const float*)d_in[25];
    const float* tlw1= (const float*)d_in[26], *tlb1= (const float*)d_in[27];
    const float* blw = (const float*)d_in[28], *blb = (const float*)d_in[29];
    float* out = (float*)d_out;

    dim3 tb(32, 8);
    k_prep<<<876, tb>>>(xyz, mw0, mw1, mw2, lw0, lw1, lw2);          // 0
    k_sample<<<BP, 128>>>(xyz, bsize, inds);                         // 1
    k_ftrans<<<dim3(625, 8, 8), tb>>>(feat);                         // 2

    int smem_b = (32*STR0 + 128*HST2) * (int)sizeof(float);          // 52224 B
    cudaFuncSetAttribute(k_mlp, cudaFuncAttributeMaxDynamicSharedMemorySize, smem_b);
    k_mlp<<<BP, 128, smem_b>>>(xyz, inds, mb0, mb1, mb2);            // 3 <- profiled

    k_label<<<BP/4, 256>>>(blabel, lb0, lb1, lb2);                   // 4
    k_emb<<<BB, 128>>>(ts);                                          // 5
    int smem_t = (8*(1024+4) + 32*132) * (int)sizeof(float);         // 49792 B
    cudaFuncSetAttribute(k_tstage, cudaFuncAttributeMaxDynamicSharedMemorySize, smem_t);
    k_tstage<<<48, 256, smem_t>>>(tw0, tb0, tlw0, tlb0, 512, 0);     // 6
    k_tstage<<<48, 256, smem_t>>>(tw1, tb1, tlw1, tlb1, 512, 1);     // 7
    k_tstage<<<24, 256, smem_t>>>(bw,  bbv, blw,  blb,  256, 2);     // 8

    const int total = BB*PP*3 + BB*128*PP + BB*256*PP + BB*PP;       // 794624
    k_out<<<(total + 255)/256, 256>>>(out, xyz, inds);               // 9
}